// round 3
// baseline (speedup 1.0000x reference)
#include <cuda_runtime.h>
#include <cstdint>

#define LL 2
#define BB 32
#define SS 2048
#define HH 512
#define DD 1024   // D = 2*H

// Scratch (no cudaMalloc allowed)
__device__ float g_ehb[BB * HH];
__device__ float g_scores[BB * SS];

__device__ __forceinline__ uint32_t f2tf32(float x) {
    uint32_t r;
    asm("cvt.rna.tf32.f32 %0, %1;" : "=r"(r) : "f"(x));
    return r;
}

// ---------------------------------------------------------------------------
// Kernel 1: ehb[b][h] = sum_d hidden[-1][b][d] * w_h[h][d] + attn_b[h]
// One warp per h. grid (H/4, B), block 128.
// ---------------------------------------------------------------------------
__global__ void ehb_kernel(const float* __restrict__ hidden,
                           const float* __restrict__ attn_w,
                           const float* __restrict__ attn_b) {
    int warp = threadIdx.x >> 5;
    int lane = threadIdx.x & 31;
    int h = blockIdx.x * 4 + warp;
    int b = blockIdx.y;
    const float* hid = hidden + (size_t)(LL - 1) * BB * DD + (size_t)b * DD;
    const float* w   = attn_w + (size_t)h * (2 * DD);  // w_h row
    float acc = 0.f;
    #pragma unroll 8
    for (int d = lane; d < DD; d += 32) acc += hid[d] * w[d];
    #pragma unroll
    for (int o = 16; o > 0; o >>= 1) acc += __shfl_xor_sync(0xffffffffu, acc, o);
    if (lane == 0) g_ehb[b * HH + h] = acc + attn_b[h];
}

// ---------------------------------------------------------------------------
// Kernel 2: scores[b][s] = sum_h v[h] * tanh(e_e[b][s][h] + ehb[b][h])
// TF32 mma.sync GEMM, BM=128 x (BN=64, looped 8x over H), BK=16.
// grid (S/BM, B), 256 threads (8 warps: 4 x 2 warp grid, 32x32 per warp).
// ---------------------------------------------------------------------------
#define BM 128
#define BN 64
#define BK 16
#define NCHUNK (HH / BN)   // 8

__global__ __launch_bounds__(256) void scores_kernel(
    const float* __restrict__ enc,
    const float* __restrict__ attn_w,
    const float* __restrict__ v_w)
{
    __shared__ uint32_t As[BK][BM + 4];
    __shared__ uint32_t Bs[BK][BN + 4];
    __shared__ float s_score[BM];

    const int b   = blockIdx.y;
    const int s0  = blockIdx.x * BM;
    const int tid = threadIdx.x;
    const int warp = tid >> 5, lane = tid & 31;
    const int wm = warp >> 1, wn = warp & 1;      // warp_m 0..3, warp_n 0..1
    const int g  = lane >> 2, tg = lane & 3;

    for (int i = tid; i < BM; i += 256) s_score[i] = 0.f;

    const float* encb = enc + ((size_t)b * SS + s0) * DD;
    const float* we   = attn_w + DD;              // w_e[h][d] = attn_w[h*2D + D + d]
    const float* ehb  = g_ehb + b * HH;

    // per-thread partial score for its 4 owned rows (same rows across n-chunks)
    float p[4] = {0.f, 0.f, 0.f, 0.f};

    const int am  = tid >> 1;            // A load: row
    const int akq = (tid & 1) * 2;       // A load: first float4 quad
    const int bn  = tid >> 2;            // B load: h row
    const int bkq = tid & 3;             // B load: float4 quad

    for (int nc = 0; nc < NCHUNK; nc++) {
        const int h0 = nc * BN;
        float acc[2][4][4];
        #pragma unroll
        for (int f = 0; f < 2; f++)
            #pragma unroll
            for (int j = 0; j < 4; j++)
                #pragma unroll
                for (int r = 0; r < 4; r++) acc[f][j][r] = 0.f;

        for (int k0 = 0; k0 < DD; k0 += BK) {
            // load A tile (enc): 128 x 16
            #pragma unroll
            for (int q = 0; q < 2; q++) {
                int kq = akq + q;
                float4 va = *(const float4*)(encb + (size_t)am * DD + k0 + kq * 4);
                As[kq * 4 + 0][am] = f2tf32(va.x);
                As[kq * 4 + 1][am] = f2tf32(va.y);
                As[kq * 4 + 2][am] = f2tf32(va.z);
                As[kq * 4 + 3][am] = f2tf32(va.w);
            }
            // load B tile (w_e): 64 x 16
            {
                float4 vb = *(const float4*)(we + (size_t)(h0 + bn) * (2 * DD) + k0 + bkq * 4);
                Bs[bkq * 4 + 0][bn] = f2tf32(vb.x);
                Bs[bkq * 4 + 1][bn] = f2tf32(vb.y);
                Bs[bkq * 4 + 2][bn] = f2tf32(vb.z);
                Bs[bkq * 4 + 3][bn] = f2tf32(vb.w);
            }
            __syncthreads();

            #pragma unroll
            for (int kk = 0; kk < BK; kk += 8) {
                uint32_t a[2][4], bfr[4][2];
                #pragma unroll
                for (int f = 0; f < 2; f++) {
                    int rm = wm * 32 + f * 16;
                    a[f][0] = As[kk + tg    ][rm + g    ];
                    a[f][1] = As[kk + tg    ][rm + g + 8];
                    a[f][2] = As[kk + tg + 4][rm + g    ];
                    a[f][3] = As[kk + tg + 4][rm + g + 8];
                }
                #pragma unroll
                for (int j = 0; j < 4; j++) {
                    int cb = wn * 32 + j * 8;
                    bfr[j][0] = Bs[kk + tg    ][cb + g];
                    bfr[j][1] = Bs[kk + tg + 4][cb + g];
                }
                #pragma unroll
                for (int f = 0; f < 2; f++)
                    #pragma unroll
                    for (int j = 0; j < 4; j++)
                        asm volatile(
                            "mma.sync.aligned.m16n8k8.row.col.f32.tf32.tf32.f32 "
                            "{%0,%1,%2,%3}, {%4,%5,%6,%7}, {%8,%9}, {%0,%1,%2,%3};"
                            : "+f"(acc[f][j][0]), "+f"(acc[f][j][1]),
                              "+f"(acc[f][j][2]), "+f"(acc[f][j][3])
                            : "r"(a[f][0]), "r"(a[f][1]), "r"(a[f][2]), "r"(a[f][3]),
                              "r"(bfr[j][0]), "r"(bfr[j][1]));
            }
            __syncthreads();
        }

        // epilogue: tanh(acc + ehb[h]) * v[h], accumulate per-row partials
        #pragma unroll
        for (int j = 0; j < 4; j++) {
            #pragma unroll
            for (int half = 0; half < 2; half++) {
                int h = h0 + wn * 32 + j * 8 + 2 * tg + half;
                float eh = ehb[h];
                float vv = v_w[h];
                #pragma unroll
                for (int f = 0; f < 2; f++) {
                    // r = half (rows g) and r = 2 + half (rows g+8)
                    p[f * 2 + 0] += tanhf(acc[f][j][half]     + eh) * vv;
                    p[f * 2 + 1] += tanhf(acc[f][j][2 + half] + eh) * vv;
                }
            }
        }
    }

    // reduce over tg (quad) then across warp_n via smem atomics
    #pragma unroll
    for (int i = 0; i < 4; i++) {
        p[i] += __shfl_xor_sync(0xffffffffu, p[i], 1);
        p[i] += __shfl_xor_sync(0xffffffffu, p[i], 2);
    }
    if (tg == 0) {
        #pragma unroll
        for (int i = 0; i < 4; i++) {
            int row = wm * 32 + (i >> 1) * 16 + g + (i & 1) * 8;
            atomicAdd(&s_score[row], p[i]);
        }
    }
    __syncthreads();
    if (tid < BM) g_scores[b * SS + s0 + tid] = s_score[tid];
}

// ---------------------------------------------------------------------------
// Kernel 3: softmax over S per batch; writes attention weights to out[B*D + ...]
// ---------------------------------------------------------------------------
__global__ __launch_bounds__(256) void softmax_kernel(float* __restrict__ out) {
    __shared__ float sh[SS];
    __shared__ float red[256];
    const int b = blockIdx.x;
    const int tid = threadIdx.x;

    float m = -1e30f;
    for (int s = tid; s < SS; s += 256) {
        float v = g_scores[b * SS + s];
        sh[s] = v;
        m = fmaxf(m, v);
    }
    red[tid] = m;
    __syncthreads();
    for (int o = 128; o > 0; o >>= 1) {
        if (tid < o) red[tid] = fmaxf(red[tid], red[tid + o]);
        __syncthreads();
    }
    const float mx = red[0];
    __syncthreads();

    float sum = 0.f;
    for (int s = tid; s < SS; s += 256) {
        float e = expf(sh[s] - mx);
        sh[s] = e;
        sum += e;
    }
    red[tid] = sum;
    __syncthreads();
    for (int o = 128; o > 0; o >>= 1) {
        if (tid < o) red[tid] += red[tid + o];
        __syncthreads();
    }
    const float inv = 1.f / red[0];
    __syncthreads();

    float* wout = out + BB * DD + (size_t)b * SS;
    for (int s = tid; s < SS; s += 256) wout[s] = sh[s] * inv;
}

// ---------------------------------------------------------------------------
// Kernel 4: context[b][d] = sum_s w[b][s] * enc[b][s][d]   (memory bound)
// grid (D/256, B), 256 threads.
// ---------------------------------------------------------------------------
__global__ __launch_bounds__(256) void context_kernel(
    const float* __restrict__ enc,
    const float* __restrict__ weights,   // out + B*D
    float* __restrict__ out)
{
    __shared__ float w[SS];
    const int b = blockIdx.y;
    const int d = blockIdx.x * 256 + threadIdx.x;
    for (int s = threadIdx.x; s < SS; s += 256) w[s] = weights[(size_t)b * SS + s];
    __syncthreads();

    const float* e = enc + (size_t)b * SS * DD + d;
    float acc = 0.f;
    #pragma unroll 8
    for (int s = 0; s < SS; s++) acc += w[s] * e[(size_t)s * DD];
    out[(size_t)b * DD + d] = acc;
}

// ---------------------------------------------------------------------------
extern "C" void kernel_launch(void* const* d_in, const int* in_sizes, int n_in,
                              void* d_out, int out_size) {
    const float* hidden = (const float*)d_in[0];
    const float* enc    = (const float*)d_in[1];
    const float* attn_w = (const float*)d_in[2];
    const float* attn_b = (const float*)d_in[3];
    const float* v_w    = (const float*)d_in[4];
    float* out = (float*)d_out;

    ehb_kernel<<<dim3(HH / 4, BB), 128>>>(hidden, attn_w, attn_b);
    scores_kernel<<<dim3(SS / BM, BB), 256>>>(enc, attn_w, v_w);
    softmax_kernel<<<BB, 256>>>(out);
    context_kernel<<<dim3(DD / 256, BB), 256>>>(enc, out + BB * DD, out);
}